// round 12
// baseline (speedup 1.0000x reference)
#include <cuda_runtime.h>
#include <cuda_bf16.h>
#include <math.h>

#define NN 4096
#define IN_DIM 1433
#define HID 64
#define OUT_DIM 7
#define MAXDEG 160
#define SCAD_A 3.7f
#define LAMW ((float)(1.0/0.9 - 1.0))
#define K_STEPS 10
#define KT 32
#define NTILE ((IN_DIM + KT - 1) / KT)   // 45
#define IBLK 512                          // persistent grid; 4 blocks/SM guaranteed

// ---------------- device globals ----------------
__device__ float  g_F0[NN * 8];
__device__ float  g_Nd[K_STEPS * NN * 8];  // one {Fn[0..6],sq} buffer PER STEP
__device__ float4 g_meta[NN];              // {rD, D, deg(bits), 0}
__device__ float  g_lam[K_STEPS];
__device__ int    g_cols[NN * MAXDEG];
__device__ unsigned g_bar_cnt;
__device__ unsigned g_bar_epoch;

typedef unsigned long long ull;

__device__ __forceinline__ ull pack_dup(float v) {
    ull r; asm("mov.b64 %0, {%1, %1};" : "=l"(r) : "f"(v)); return r;
}
__device__ __forceinline__ void fma2(ull& d, ull a, ull b) {
    asm("fma.rn.f32x2 %0, %1, %2, %0;" : "+l"(d) : "l"(a), "l"(b));
}
__device__ __forceinline__ void unpack2(ull p, float& lo, float& hi) {
    asm("mov.b64 {%0, %1}, %2;" : "=f"(lo), "=f"(hi) : "l"(p));
}
__device__ __forceinline__ float shx(float v, int m) {
    return __shfl_xor_sync(0xffffffffu, v, m);
}

// ============================================================================
// Kernel A: block-specialized — blocks [0,512): adjacency (1 row/warp);
//           blocks [512,640): MLP (32 rows/block).  No cross dependency:
//           mlp writes F0 only; Nd seed moved to the persistent kernel.
// ============================================================================
__global__ __launch_bounds__(256)
void fused_prep(const float* __restrict__ A,
                const float* __restrict__ X,
                const float* __restrict__ w1,
                const float* __restrict__ b1,
                const float* __restrict__ w2,
                const float* __restrict__ b2,
                const float* __restrict__ lg0p,
                const float* __restrict__ rawp) {
    __shared__ __align__(16) ull   Xd[2][KT][33];
    __shared__ __align__(16) float Wsm[2][KT][HID];
    __shared__ float Hs[32][65];
    __shared__ float F0s[32][8];
    __shared__ float w2s[HID * OUT_DIM];
    __shared__ float b2s[OUT_DIM];
    int tid = threadIdx.x;

    if (blockIdx.x < 512) {
        // -------------------- adjacency: one row per warp ------------------
        int warp = tid >> 5, lane = tid & 31;
        int r = blockIdx.x * 8 + warp;
        const float4* row4 = (const float4*)(A + (size_t)r * NN);
        int* cols = g_cols + (size_t)r * MAXDEG;
        unsigned below = (1u << lane) - 1u;
        int cnt = 0;

        #pragma unroll 2
        for (int c0 = 0; c0 < NN; c0 += 256) {
            float4 va = row4[(c0 >> 2) + lane];
            float4 vb = row4[(c0 >> 2) + 32 + lane];
            unsigned mk = 0;
            mk |= (va.x != 0.0f) ? 1u   : 0u;
            mk |= (va.y != 0.0f) ? 2u   : 0u;
            mk |= (va.z != 0.0f) ? 4u   : 0u;
            mk |= (va.w != 0.0f) ? 8u   : 0u;
            mk |= (vb.x != 0.0f) ? 16u  : 0u;
            mk |= (vb.y != 0.0f) ? 32u  : 0u;
            mk |= (vb.z != 0.0f) ? 64u  : 0u;
            mk |= (vb.w != 0.0f) ? 128u : 0u;
            int c = __popc(mk);
            int pre = 0, tot = 0;
            #pragma unroll
            for (int t = 0; t < 4; t++) {
                unsigned m = __ballot_sync(0xffffffffu, (c >> t) & 1);
                pre += __popc(m & below) << t;
                tot += __popc(m) << t;
            }
            int base = cnt + pre;
            cnt += tot;
            if (mk) {
                int cA = c0 + lane * 4, cB = c0 + 128 + lane * 4;
                if (mk & 1u)   { if (base < MAXDEG) cols[base] = cA + 0; base++; }
                if (mk & 2u)   { if (base < MAXDEG) cols[base] = cA + 1; base++; }
                if (mk & 4u)   { if (base < MAXDEG) cols[base] = cA + 2; base++; }
                if (mk & 8u)   { if (base < MAXDEG) cols[base] = cA + 3; base++; }
                if (mk & 16u)  { if (base < MAXDEG) cols[base] = cB + 0; base++; }
                if (mk & 32u)  { if (base < MAXDEG) cols[base] = cB + 1; base++; }
                if (mk & 64u)  { if (base < MAXDEG) cols[base] = cB + 2; base++; }
                if (mk & 128u) { if (base < MAXDEG) cols[base] = cB + 3; base++; }
            }
        }
        if (lane == 0) {
            int d = cnt < MAXDEG ? cnt : MAXDEG;
            float D = (float)cnt + 1.0f;    // self loop
            g_meta[r] = make_float4(1.0f / sqrtf(D), D, __int_as_float(d), 0.0f);
        }
        if (blockIdx.x == 0 && tid == 0) {
            float g0 = expf(lg0p[0]);
            float rr = 1.0f / (1.0f + expf(-rawp[0]));
            float gk = g0;
            #pragma unroll
            for (int k = 0; k < K_STEPS; k++) { g_lam[k] = gk / SCAD_A; gk *= rr; }
        }
        return;
    }

    // -------------------- MLP: H = relu(X@w1+b1); F0 = H@w2+b2 -------------
    int m0 = (blockIdx.x - 512) * 32;
    int tx = tid & 15;
    int ty = tid >> 4;
    ull acc[2][2] = {{0ull, 0ull}, {0ull, 0ull}};

    for (int idx = tid; idx < HID * OUT_DIM; idx += 256) w2s[idx] = w2[idx];
    if (tid >= 256 - OUT_DIM) b2s[tid - (256 - OUT_DIM)] = b2[tid - (256 - OUT_DIM)];

    float xr0, xr1, xr2, xr3;
    int xrow = tid >> 3;
    int xk   = (tid & 7) * 4;
    float4 wr[2];
    const float* xrow_p = X + (size_t)(m0 + xrow) * IN_DIM;
    {
        xr0 = xrow_p[xk + 0]; xr1 = xrow_p[xk + 1];
        xr2 = xrow_p[xk + 2]; xr3 = xrow_p[xk + 3];
        #pragma unroll
        for (int j = 0; j < 2; j++) {
            int f4 = tid + j * 256;
            int k = f4 >> 4, n4 = f4 & 15;
            wr[j] = *(const float4*)(w1 + (size_t)k * HID + n4 * 4);
        }
    }

    for (int t = 0; t < NTILE; t++) {
        int buf = t & 1;
        __syncthreads();
        Xd[buf][xk + 0][xrow] = pack_dup(xr0);
        Xd[buf][xk + 1][xrow] = pack_dup(xr1);
        Xd[buf][xk + 2][xrow] = pack_dup(xr2);
        Xd[buf][xk + 3][xrow] = pack_dup(xr3);
        #pragma unroll
        for (int j = 0; j < 2; j++) {
            int f4 = tid + j * 256;
            int k = f4 >> 4, n4 = f4 & 15;
            *(float4*)&Wsm[buf][k][n4 * 4] = wr[j];
        }
        if (t + 1 < NTILE) {
            int kt = (t + 1) * KT;
            if (kt + KT <= IN_DIM) {
                xr0 = xrow_p[kt + xk + 0]; xr1 = xrow_p[kt + xk + 1];
                xr2 = xrow_p[kt + xk + 2]; xr3 = xrow_p[kt + xk + 3];
                #pragma unroll
                for (int j = 0; j < 2; j++) {
                    int f4 = tid + j * 256;
                    int k = kt + (f4 >> 4), n4 = f4 & 15;
                    wr[j] = *(const float4*)(w1 + (size_t)k * HID + n4 * 4);
                }
            } else {
                xr0 = (kt + xk + 0 < IN_DIM) ? xrow_p[kt + xk + 0] : 0.0f;
                xr1 = (kt + xk + 1 < IN_DIM) ? xrow_p[kt + xk + 1] : 0.0f;
                xr2 = (kt + xk + 2 < IN_DIM) ? xrow_p[kt + xk + 2] : 0.0f;
                xr3 = (kt + xk + 3 < IN_DIM) ? xrow_p[kt + xk + 3] : 0.0f;
                #pragma unroll
                for (int j = 0; j < 2; j++) {
                    int f4 = tid + j * 256;
                    int k = kt + (f4 >> 4), n4 = f4 & 15;
                    wr[j] = (k < IN_DIM)
                          ? *(const float4*)(w1 + (size_t)k * HID + n4 * 4)
                          : make_float4(0.f, 0.f, 0.f, 0.f);
                }
            }
        }
        __syncthreads();
        #pragma unroll
        for (int k = 0; k < KT; k++) {
            ull ar0 = Xd[buf][k][ty * 2];
            ull ar1 = Xd[buf][k][ty * 2 + 1];
            ulonglong2 b = *(const ulonglong2*)&Wsm[buf][k][tx * 4];
            fma2(acc[0][0], ar0, b.x);
            fma2(acc[0][1], ar0, b.y);
            fma2(acc[1][0], ar1, b.x);
            fma2(acc[1][1], ar1, b.y);
        }
    }

    float4 bv = *(const float4*)&b1[tx * 4];
    #pragma unroll
    for (int r = 0; r < 2; r++) {
        int rl = ty * 2 + r;
        float o0, o1, o2, o3;
        unpack2(acc[r][0], o0, o1);
        unpack2(acc[r][1], o2, o3);
        Hs[rl][tx * 4 + 0] = fmaxf(o0 + bv.x, 0.0f);
        Hs[rl][tx * 4 + 1] = fmaxf(o1 + bv.y, 0.0f);
        Hs[rl][tx * 4 + 2] = fmaxf(o2 + bv.z, 0.0f);
        Hs[rl][tx * 4 + 3] = fmaxf(o3 + bv.w, 0.0f);
    }
    __syncthreads();

    if (tid < 32 * OUT_DIM) {
        int o = tid >> 5, r = tid & 31;
        float a = b2s[o];
        #pragma unroll 16
        for (int k = 0; k < HID; k++) a = fmaf(Hs[r][k], w2s[k * OUT_DIM + o], a);
        F0s[r][o] = a;
    }
    __syncthreads();

    if (tid < 32) {
        int row = m0 + tid;
        #pragma unroll
        for (int o = 0; o < 7; o++) g_F0[row * 8 + o] = F0s[tid][o];
        g_F0[row * 8 + 7] = 0.0f;
    }
}

// ============================================================================
// Kernel B: persistent iterations — 512 blocks x 256 threads, warp per row.
// One Nd buffer PER STEP: every buffer written once (st.cg) and read once an
// iteration later via normal cached loads. A reader SM can never hold a stale
// L1 line for a first-touch address, so full L1 reuse of gathers is safe, and
// cols/meta/F0 stay L1-hot across all steps (no per-launch flush).
// ============================================================================
__device__ __forceinline__ void bar_arrive_wait(unsigned target_epoch) {
    __syncthreads();
    if (threadIdx.x == 0) {
        unsigned old;
        asm volatile("atom.add.acq_rel.gpu.u32 %0, [%1], %2;"
                     : "=r"(old) : "l"(&g_bar_cnt), "r"(1u) : "memory");
        if (old == target_epoch * (unsigned)IBLK - 1u) {
            asm volatile("st.release.gpu.u32 [%0], %1;"
                         :: "l"(&g_bar_epoch), "r"(target_epoch) : "memory");
        } else {
            unsigned e;
            do {
                asm volatile("ld.acquire.gpu.u32 %0, [%1];"
                             : "=r"(e) : "l"(&g_bar_epoch) : "memory");
            } while ((int)(e - target_epoch) < 0);
        }
    }
    __syncthreads();
}

__global__ __launch_bounds__(256, 4)
void iter_persistent(float* __restrict__ out) {
    __shared__ unsigned ep0s;
    int tid = threadIdx.x;
    int lane = tid & 31;
    int g = lane & 7;
    int i = blockIdx.x * 8 + (tid >> 5);     // warp per row

    if (tid == 0) {
        unsigned e;
        asm volatile("ld.acquire.gpu.u32 %0, [%1];" : "=r"(e)
                     : "l"(&g_bar_epoch) : "memory");
        ep0s = e;
    }

    // loop-invariant row state (stays in regs / L1 for all steps)
    float4 meta = g_meta[i];
    float rdi = meta.x, Di = meta.y;
    int deg = __float_as_int(meta.z);
    float F0g = g_F0[(size_t)i * 8 + g];     // slot 7 = 0
    const int* cols = g_cols + (size_t)i * MAXDEG;
    __syncthreads();
    unsigned ep0 = ep0s;

    // ---- prologue: seed buf 0 with {Fn = F0/sqrt(D), sq} ----
    {
        float fn = F0g * rdi;                // g==7 -> 0
        float c = (g < 7) ? fn * fn : 0.0f;
        c += shx(c, 1);
        c += shx(c, 2);
        c += shx(c, 4);
        if (lane < 8)
            __stcg(&g_Nd[(size_t)i * 8 + g], (g < 7) ? fn : c);
    }
    bar_arrive_wait(ep0 + 1);

    #pragma unroll 1
    for (int k = 0; k < K_STEPS; k++) {
        const float* Ndin  = g_Nd + (size_t)k * (NN * 8);
        float*       Ndout = g_Nd + (size_t)(k + 1) * (NN * 8);
        float lam = g_lam[k];
        float alam = SCAD_A * lam;

        const float4* ndi = (const float4*)(Ndin + (size_t)i * 8);
        float4 f0 = ndi[0], f1 = ndi[1];
        float fni[7] = {f0.x, f0.y, f0.z, f0.w, f1.x, f1.y, f1.z};
        float sqi = f1.w;

        float t0 = 0.f, t1 = 0.f, t2 = 0.f, t3 = 0.f,
              t4 = 0.f, t5 = 0.f, t6 = 0.f, t7 = 0.f;   // t7 = s

        for (int e = lane; e < deg; e += 32) {
            int j = cols[e];
            const float4* nj = (const float4*)(Ndin + (size_t)j * 8);
            float4 a0 = nj[0], a1 = nj[1];
            float dot = fni[0] * a0.x + fni[1] * a0.y + fni[2] * a0.z
                      + fni[3] * a0.w + fni[4] * a1.x + fni[5] * a1.y
                      + fni[6] * a1.z;
            float Z = fmaxf(sqi + a1.w - 2.0f * dot, 0.0f);
            float y = sqrtf(Z);
            float w;
            if (y <= lam)        w = 1.0f;
            else if (y <= alam)  w = __fdividef(alam - y,
                                                (SCAD_A - 1.0f) * fmaxf(y, 1e-12f));
            else                 w = 0.0f;
            t7 += w;
            t0 = fmaf(w, a0.x, t0);
            t1 = fmaf(w, a0.y, t1);
            t2 = fmaf(w, a0.z, t2);
            t3 = fmaf(w, a0.w, t3);
            t4 = fmaf(w, a1.x, t4);
            t5 = fmaf(w, a1.y, t5);
            t6 = fmaf(w, a1.z, t6);
        }

        // transposing tree reduce within each 8-lane group (7 shfls)
        bool h4 = (g & 4) != 0, h2 = (g & 2) != 0, h1 = (g & 1) != 0;
        float r0 = shx(h4 ? t0 : t4, 4);
        float r1 = shx(h4 ? t1 : t5, 4);
        float r2 = shx(h4 ? t2 : t6, 4);
        float r3 = shx(h4 ? t3 : t7, 4);
        float u0 = (h4 ? t4 : t0) + r0;
        float u1 = (h4 ? t5 : t1) + r1;
        float u2 = (h4 ? t6 : t2) + r2;
        float u3 = (h4 ? t7 : t3) + r3;
        r0 = shx(h2 ? u0 : u2, 2);
        r1 = shx(h2 ? u1 : u3, 2);
        float w0 = (h2 ? u2 : u0) + r0;
        float w1 = (h2 ? u3 : u1) + r1;
        r0 = shx(h1 ? w0 : w1, 1);
        float tot = (h1 ? w1 : w0) + r0;
        tot += shx(tot, 8);
        tot += shx(tot, 16);

        float sT = __shfl_sync(0xffffffffu, tot, 7, 8);   // comp 7 = s
        float Q = sT / Di + LAMW;
        float invQ = 1.0f / Q;
        float f = (rdi * tot + LAMW * F0g) * invQ;

        if (k == K_STEPS - 1) {
            if (lane < 7) out[(size_t)i * OUT_DIM + g] = f;
        } else {
            float fn = f * rdi;
            float c = (g < 7) ? fn * fn : 0.0f;
            c += shx(c, 1);
            c += shx(c, 2);
            c += shx(c, 4);
            if (lane < 8)
                __stcg(&Ndout[(size_t)i * 8 + g], (g < 7) ? fn : c);
            bar_arrive_wait(ep0 + 2 + (unsigned)k);
        }
    }
}

// ---------------- launch ----------------
extern "C" void kernel_launch(void* const* d_in, const int* in_sizes, int n_in,
                              void* d_out, int out_size) {
    const float *A = nullptr, *X = nullptr, *w1 = nullptr, *b1 = nullptr,
                *w2 = nullptr, *b2 = nullptr, *lg0 = nullptr, *raw = nullptr;
    for (int t = 0; t < n_in; t++) {
        int sz = in_sizes[t];
        const float* p = (const float*)d_in[t];
        if      (sz == NN * NN)        A  = p;
        else if (sz == NN * IN_DIM)    X  = p;
        else if (sz == IN_DIM * HID)   w1 = p;
        else if (sz == HID)            b1 = p;
        else if (sz == HID * OUT_DIM)  w2 = p;
        else if (sz == OUT_DIM)        b2 = p;
        else if (sz == 1) { if (!lg0) lg0 = p; else raw = p; }
    }
    float* out = (float*)d_out;

    fused_prep<<<640, 256>>>(A, X, w1, b1, w2, b2, lg0, raw);
    iter_persistent<<<IBLK, 256>>>(out);
}

// round 13
// speedup vs baseline: 1.2473x; 1.2473x over previous
#include <cuda_runtime.h>
#include <cuda_bf16.h>
#include <math.h>

#define NN 4096
#define IN_DIM 1433
#define HID 64
#define OUT_DIM 7
#define MAXDEG 160
#define SCAD_A 3.7f
#define LAMW ((float)(1.0/0.9 - 1.0))
#define K_STEPS 10
#define KT 32
#define NTILE ((IN_DIM + KT - 1) / KT)   // 45
#define IBLK 512                          // persistent grid; 4 blocks/SM guaranteed

// ---------------- device globals ----------------
__device__ float  g_F0[NN * 8];
__device__ float  g_Nd[(K_STEPS + 1) * NN * 8];  // one {Fn[0..6],sq} buffer per step
__device__ float4 g_meta[NN];              // {rD, D, deg(bits), 0}
__device__ float  g_lam[K_STEPS];
__device__ int    g_cols[NN * MAXDEG];
__device__ unsigned g_bar_cnt;
__device__ unsigned g_bar_epoch;

typedef unsigned long long ull;

__device__ __forceinline__ ull pack_dup(float v) {
    ull r; asm("mov.b64 %0, {%1, %1};" : "=l"(r) : "f"(v)); return r;
}
__device__ __forceinline__ void fma2(ull& d, ull a, ull b) {
    asm("fma.rn.f32x2 %0, %1, %2, %0;" : "+l"(d) : "l"(a), "l"(b));
}
__device__ __forceinline__ void unpack2(ull p, float& lo, float& hi) {
    asm("mov.b64 {%0, %1}, %2;" : "=f"(lo), "=f"(hi) : "l"(p));
}
__device__ __forceinline__ float shx(float v, int m) {
    return __shfl_xor_sync(0xffffffffu, v, m);
}

// ============================================================================
// Kernel 1: adjacency — one row per warp, 512 blocks x 256 threads (R10 form)
// ============================================================================
__global__ __launch_bounds__(256)
void build_adj(const float* __restrict__ A,
               const float* __restrict__ lg0p,
               const float* __restrict__ rawp) {
    int warp = threadIdx.x >> 5, lane = threadIdx.x & 31;
    int r = blockIdx.x * 8 + warp;
    const float4* row4 = (const float4*)(A + (size_t)r * NN);
    int* cols = g_cols + (size_t)r * MAXDEG;
    unsigned below = (1u << lane) - 1u;
    int cnt = 0;

    #pragma unroll 2
    for (int c0 = 0; c0 < NN; c0 += 256) {
        float4 va = row4[(c0 >> 2) + lane];
        float4 vb = row4[(c0 >> 2) + 32 + lane];
        unsigned mk = 0;
        mk |= (va.x != 0.0f) ? 1u   : 0u;
        mk |= (va.y != 0.0f) ? 2u   : 0u;
        mk |= (va.z != 0.0f) ? 4u   : 0u;
        mk |= (va.w != 0.0f) ? 8u   : 0u;
        mk |= (vb.x != 0.0f) ? 16u  : 0u;
        mk |= (vb.y != 0.0f) ? 32u  : 0u;
        mk |= (vb.z != 0.0f) ? 64u  : 0u;
        mk |= (vb.w != 0.0f) ? 128u : 0u;
        int c = __popc(mk);
        int pre = 0, tot = 0;
        #pragma unroll
        for (int t = 0; t < 4; t++) {
            unsigned m = __ballot_sync(0xffffffffu, (c >> t) & 1);
            pre += __popc(m & below) << t;
            tot += __popc(m) << t;
        }
        int base = cnt + pre;
        cnt += tot;
        if (mk) {
            int cA = c0 + lane * 4, cB = c0 + 128 + lane * 4;
            if (mk & 1u)   { if (base < MAXDEG) cols[base] = cA + 0; base++; }
            if (mk & 2u)   { if (base < MAXDEG) cols[base] = cA + 1; base++; }
            if (mk & 4u)   { if (base < MAXDEG) cols[base] = cA + 2; base++; }
            if (mk & 8u)   { if (base < MAXDEG) cols[base] = cA + 3; base++; }
            if (mk & 16u)  { if (base < MAXDEG) cols[base] = cB + 0; base++; }
            if (mk & 32u)  { if (base < MAXDEG) cols[base] = cB + 1; base++; }
            if (mk & 64u)  { if (base < MAXDEG) cols[base] = cB + 2; base++; }
            if (mk & 128u) { if (base < MAXDEG) cols[base] = cB + 3; base++; }
        }
    }
    if (lane == 0) {
        int d = cnt < MAXDEG ? cnt : MAXDEG;
        float D = (float)cnt + 1.0f;    // self loop
        g_meta[r] = make_float4(1.0f / sqrtf(D), D, __int_as_float(d), 0.0f);
    }
    if (blockIdx.x == 0 && threadIdx.x == 0) {
        float g0 = expf(lg0p[0]);
        float rr = 1.0f / (1.0f + expf(-rawp[0]));
        float gk = g0;
        #pragma unroll
        for (int k = 0; k < K_STEPS; k++) { g_lam[k] = gk / SCAD_A; gk *= rr; }
    }
}

// ============================================================================
// Kernel 2: mlp_fused — H = relu(X@w1+b1) in smem; F0 = H@w2+b2 (F0 only;
// Nd seed happens in the persistent kernel's prologue)
// 128 blocks x 256 threads, 32 rows per block
// ============================================================================
__global__ __launch_bounds__(256, 2)
void mlp_fused(const float* __restrict__ X,
               const float* __restrict__ w1,
               const float* __restrict__ b1,
               const float* __restrict__ w2,
               const float* __restrict__ b2) {
    __shared__ __align__(16) ull   Xd[2][KT][33];
    __shared__ __align__(16) float Wsm[2][KT][HID];
    __shared__ float Hs[32][65];
    __shared__ float F0s[32][8];
    __shared__ float w2s[HID * OUT_DIM];
    __shared__ float b2s[OUT_DIM];
    int tid = threadIdx.x;
    int m0 = blockIdx.x * 32;
    int tx = tid & 15;
    int ty = tid >> 4;
    ull acc[2][2] = {{0ull, 0ull}, {0ull, 0ull}};

    for (int idx = tid; idx < HID * OUT_DIM; idx += 256) w2s[idx] = w2[idx];
    if (tid >= 256 - OUT_DIM) b2s[tid - (256 - OUT_DIM)] = b2[tid - (256 - OUT_DIM)];

    float xr0, xr1, xr2, xr3;
    int xrow = tid >> 3;
    int xk   = (tid & 7) * 4;
    float4 wr[2];
    const float* xrow_p = X + (size_t)(m0 + xrow) * IN_DIM;
    {
        xr0 = xrow_p[xk + 0]; xr1 = xrow_p[xk + 1];
        xr2 = xrow_p[xk + 2]; xr3 = xrow_p[xk + 3];
        #pragma unroll
        for (int j = 0; j < 2; j++) {
            int f4 = tid + j * 256;
            int k = f4 >> 4, n4 = f4 & 15;
            wr[j] = *(const float4*)(w1 + (size_t)k * HID + n4 * 4);
        }
    }

    for (int t = 0; t < NTILE; t++) {
        int buf = t & 1;
        __syncthreads();
        Xd[buf][xk + 0][xrow] = pack_dup(xr0);
        Xd[buf][xk + 1][xrow] = pack_dup(xr1);
        Xd[buf][xk + 2][xrow] = pack_dup(xr2);
        Xd[buf][xk + 3][xrow] = pack_dup(xr3);
        #pragma unroll
        for (int j = 0; j < 2; j++) {
            int f4 = tid + j * 256;
            int k = f4 >> 4, n4 = f4 & 15;
            *(float4*)&Wsm[buf][k][n4 * 4] = wr[j];
        }
        if (t + 1 < NTILE) {
            int kt = (t + 1) * KT;
            if (kt + KT <= IN_DIM) {
                xr0 = xrow_p[kt + xk + 0]; xr1 = xrow_p[kt + xk + 1];
                xr2 = xrow_p[kt + xk + 2]; xr3 = xrow_p[kt + xk + 3];
                #pragma unroll
                for (int j = 0; j < 2; j++) {
                    int f4 = tid + j * 256;
                    int k = kt + (f4 >> 4), n4 = f4 & 15;
                    wr[j] = *(const float4*)(w1 + (size_t)k * HID + n4 * 4);
                }
            } else {
                xr0 = (kt + xk + 0 < IN_DIM) ? xrow_p[kt + xk + 0] : 0.0f;
                xr1 = (kt + xk + 1 < IN_DIM) ? xrow_p[kt + xk + 1] : 0.0f;
                xr2 = (kt + xk + 2 < IN_DIM) ? xrow_p[kt + xk + 2] : 0.0f;
                xr3 = (kt + xk + 3 < IN_DIM) ? xrow_p[kt + xk + 3] : 0.0f;
                #pragma unroll
                for (int j = 0; j < 2; j++) {
                    int f4 = tid + j * 256;
                    int k = kt + (f4 >> 4), n4 = f4 & 15;
                    wr[j] = (k < IN_DIM)
                          ? *(const float4*)(w1 + (size_t)k * HID + n4 * 4)
                          : make_float4(0.f, 0.f, 0.f, 0.f);
                }
            }
        }
        __syncthreads();
        #pragma unroll
        for (int k = 0; k < KT; k++) {
            ull ar0 = Xd[buf][k][ty * 2];
            ull ar1 = Xd[buf][k][ty * 2 + 1];
            ulonglong2 b = *(const ulonglong2*)&Wsm[buf][k][tx * 4];
            fma2(acc[0][0], ar0, b.x);
            fma2(acc[0][1], ar0, b.y);
            fma2(acc[1][0], ar1, b.x);
            fma2(acc[1][1], ar1, b.y);
        }
    }

    float4 bv = *(const float4*)&b1[tx * 4];
    #pragma unroll
    for (int r = 0; r < 2; r++) {
        int rl = ty * 2 + r;
        float o0, o1, o2, o3;
        unpack2(acc[r][0], o0, o1);
        unpack2(acc[r][1], o2, o3);
        Hs[rl][tx * 4 + 0] = fmaxf(o0 + bv.x, 0.0f);
        Hs[rl][tx * 4 + 1] = fmaxf(o1 + bv.y, 0.0f);
        Hs[rl][tx * 4 + 2] = fmaxf(o2 + bv.z, 0.0f);
        Hs[rl][tx * 4 + 3] = fmaxf(o3 + bv.w, 0.0f);
    }
    __syncthreads();

    if (tid < 32 * OUT_DIM) {
        int o = tid >> 5, r = tid & 31;
        float a = b2s[o];
        #pragma unroll 16
        for (int k = 0; k < HID; k++) a = fmaf(Hs[r][k], w2s[k * OUT_DIM + o], a);
        F0s[r][o] = a;
    }
    __syncthreads();

    if (tid < 32) {
        int row = m0 + tid;
        #pragma unroll
        for (int o = 0; o < 7; o++) g_F0[row * 8 + o] = F0s[tid][o];
        g_F0[row * 8 + 7] = 0.0f;
    }
}

// ============================================================================
// Kernel 3: persistent iterations — 512 blocks x 256 threads, warp per row.
// One Nd buffer per step (written once via st.cg, read once next step via
// cached loads: reader first-touch => no stale-L1 hazard, full L1 gather reuse;
// cols/meta/F0 L1-hot across all 10 steps). Epoch acq_rel barrier between steps.
// ============================================================================
__device__ __forceinline__ void bar_arrive_wait(unsigned target_epoch) {
    __syncthreads();
    if (threadIdx.x == 0) {
        unsigned old;
        asm volatile("atom.add.acq_rel.gpu.u32 %0, [%1], %2;"
                     : "=r"(old) : "l"(&g_bar_cnt), "r"(1u) : "memory");
        if (old == target_epoch * (unsigned)IBLK - 1u) {
            asm volatile("st.release.gpu.u32 [%0], %1;"
                         :: "l"(&g_bar_epoch), "r"(target_epoch) : "memory");
        } else {
            unsigned e;
            do {
                asm volatile("ld.acquire.gpu.u32 %0, [%1];"
                             : "=r"(e) : "l"(&g_bar_epoch) : "memory");
            } while ((int)(e - target_epoch) < 0);
        }
    }
    __syncthreads();
}

__global__ __launch_bounds__(256, 4)
void iter_persistent(float* __restrict__ out) {
    __shared__ unsigned ep0s;
    int tid = threadIdx.x;
    int lane = tid & 31;
    int g = lane & 7;
    int i = blockIdx.x * 8 + (tid >> 5);     // warp per row

    if (tid == 0) {
        unsigned e;
        asm volatile("ld.acquire.gpu.u32 %0, [%1];" : "=r"(e)
                     : "l"(&g_bar_epoch) : "memory");
        ep0s = e;
    }

    // loop-invariant row state
    float4 meta = g_meta[i];
    float rdi = meta.x, Di = meta.y;
    int deg = __float_as_int(meta.z);
    float F0g = g_F0[(size_t)i * 8 + g];     // slot 7 = 0
    const int* cols = g_cols + (size_t)i * MAXDEG;
    __syncthreads();
    unsigned ep0 = ep0s;

    // ---- prologue: seed buf 0 with {Fn = F0/sqrt(D), sq} ----
    {
        float fn = F0g * rdi;                // g==7 -> 0
        float c = (g < 7) ? fn * fn : 0.0f;
        c += shx(c, 1);
        c += shx(c, 2);
        c += shx(c, 4);
        if (lane < 8)
            __stcg(&g_Nd[(size_t)i * 8 + g], (g < 7) ? fn : c);
    }
    bar_arrive_wait(ep0 + 1);

    #pragma unroll 1
    for (int k = 0; k < K_STEPS; k++) {
        const float* Ndin  = g_Nd + (size_t)k * (NN * 8);
        float*       Ndout = g_Nd + (size_t)(k + 1) * (NN * 8);
        float lam = g_lam[k];
        float alam = SCAD_A * lam;

        const float4* ndi = (const float4*)(Ndin + (size_t)i * 8);
        float4 f0 = ndi[0], f1 = ndi[1];
        float fni[7] = {f0.x, f0.y, f0.z, f0.w, f1.x, f1.y, f1.z};
        float sqi = f1.w;

        float t0 = 0.f, t1 = 0.f, t2 = 0.f, t3 = 0.f,
              t4 = 0.f, t5 = 0.f, t6 = 0.f, t7 = 0.f;   // t7 = s

        for (int e = lane; e < deg; e += 32) {
            int j = cols[e];
            const float4* nj = (const float4*)(Ndin + (size_t)j * 8);
            float4 a0 = nj[0], a1 = nj[1];
            float dot = fni[0] * a0.x + fni[1] * a0.y + fni[2] * a0.z
                      + fni[3] * a0.w + fni[4] * a1.x + fni[5] * a1.y
                      + fni[6] * a1.z;
            float Z = fmaxf(sqi + a1.w - 2.0f * dot, 0.0f);
            float y = sqrtf(Z);
            float w;
            if (y <= lam)        w = 1.0f;
            else if (y <= alam)  w = __fdividef(alam - y,
                                                (SCAD_A - 1.0f) * fmaxf(y, 1e-12f));
            else                 w = 0.0f;
            t7 += w;
            t0 = fmaf(w, a0.x, t0);
            t1 = fmaf(w, a0.y, t1);
            t2 = fmaf(w, a0.z, t2);
            t3 = fmaf(w, a0.w, t3);
            t4 = fmaf(w, a1.x, t4);
            t5 = fmaf(w, a1.y, t5);
            t6 = fmaf(w, a1.z, t6);
        }

        // transposing tree reduce within each 8-lane group (7 shfls)
        bool h4 = (g & 4) != 0, h2 = (g & 2) != 0, h1 = (g & 1) != 0;
        float r0 = shx(h4 ? t0 : t4, 4);
        float r1 = shx(h4 ? t1 : t5, 4);
        float r2 = shx(h4 ? t2 : t6, 4);
        float r3 = shx(h4 ? t3 : t7, 4);
        float u0 = (h4 ? t4 : t0) + r0;
        float u1 = (h4 ? t5 : t1) + r1;
        float u2 = (h4 ? t6 : t2) + r2;
        float u3 = (h4 ? t7 : t3) + r3;
        r0 = shx(h2 ? u0 : u2, 2);
        r1 = shx(h2 ? u1 : u3, 2);
        float w0 = (h2 ? u2 : u0) + r0;
        float w1 = (h2 ? u3 : u1) + r1;
        r0 = shx(h1 ? w0 : w1, 1);
        float tot = (h1 ? w1 : w0) + r0;
        tot += shx(tot, 8);
        tot += shx(tot, 16);

        float sT = __shfl_sync(0xffffffffu, tot, 7, 8);   // comp 7 = s
        float Q = sT / Di + LAMW;
        float invQ = 1.0f / Q;
        float f = (rdi * tot + LAMW * F0g) * invQ;

        if (k == K_STEPS - 1) {
            if (lane < 7) out[(size_t)i * OUT_DIM + g] = f;
        } else {
            float fn = f * rdi;
            float c = (g < 7) ? fn * fn : 0.0f;
            c += shx(c, 1);
            c += shx(c, 2);
            c += shx(c, 4);
            if (lane < 8)
                __stcg(&Ndout[(size_t)i * 8 + g], (g < 7) ? fn : c);
            bar_arrive_wait(ep0 + 2 + (unsigned)k);
        }
    }
}

// ---------------- launch ----------------
extern "C" void kernel_launch(void* const* d_in, const int* in_sizes, int n_in,
                              void* d_out, int out_size) {
    const float *A = nullptr, *X = nullptr, *w1 = nullptr, *b1 = nullptr,
                *w2 = nullptr, *b2 = nullptr, *lg0 = nullptr, *raw = nullptr;
    for (int t = 0; t < n_in; t++) {
        int sz = in_sizes[t];
        const float* p = (const float*)d_in[t];
        if      (sz == NN * NN)        A  = p;
        else if (sz == NN * IN_DIM)    X  = p;
        else if (sz == IN_DIM * HID)   w1 = p;
        else if (sz == HID)            b1 = p;
        else if (sz == HID * OUT_DIM)  w2 = p;
        else if (sz == OUT_DIM)        b2 = p;
        else if (sz == 1) { if (!lg0) lg0 = p; else raw = p; }
    }
    float* out = (float*)d_out;

    build_adj<<<512, 256>>>(A, lg0, raw);
    mlp_fused<<<128, 256>>>(X, w1, b1, w2, b2);
    iter_persistent<<<IBLK, 256>>>(out);
}

// round 14
// speedup vs baseline: 1.2641x; 1.0135x over previous
#include <cuda_runtime.h>
#include <cuda_bf16.h>
#include <math.h>

#define NN 4096
#define IN_DIM 1433
#define HID 64
#define OUT_DIM 7
#define MAXDEG 160
#define SCAD_A 3.7f
#define LAMW ((float)(1.0/0.9 - 1.0))
#define K_STEPS 10
#define KT 32
#define NTILE ((IN_DIM + KT - 1) / KT)   // 45
#define TSPLIT 23                         // group0 tiles [0,23), group1 [23,45)
#define IBLK 512                          // persistent grid; 4 blocks/SM guaranteed

// ---------------- device globals ----------------
__device__ float  g_F0[NN * 8];
__device__ float  g_Nd[(K_STEPS + 1) * NN * 8];  // one {Fn[0..6],sq} buffer per step
__device__ float4 g_meta[NN];              // {rD, D, deg(bits), 0}
__device__ float  g_lam[K_STEPS];
__device__ int    g_cols[NN * MAXDEG];
__device__ unsigned g_bar_cnt;
__device__ unsigned g_bar_epoch;

typedef unsigned long long ull;

__device__ __forceinline__ ull pack_dup(float v) {
    ull r; asm("mov.b64 %0, {%1, %1};" : "=l"(r) : "f"(v)); return r;
}
__device__ __forceinline__ void fma2(ull& d, ull a, ull b) {
    asm("fma.rn.f32x2 %0, %1, %2, %0;" : "+l"(d) : "l"(a), "l"(b));
}
__device__ __forceinline__ void unpack2(ull p, float& lo, float& hi) {
    asm("mov.b64 {%0, %1}, %2;" : "=f"(lo), "=f"(hi) : "l"(p));
}
__device__ __forceinline__ float shx(float v, int m) {
    return __shfl_xor_sync(0xffffffffu, v, m);
}

// ============================================================================
// Kernel 1: adjacency — one row per warp, 512 blocks x 256 threads
// ============================================================================
__global__ __launch_bounds__(256)
void build_adj(const float* __restrict__ A,
               const float* __restrict__ lg0p,
               const float* __restrict__ rawp) {
    int warp = threadIdx.x >> 5, lane = threadIdx.x & 31;
    int r = blockIdx.x * 8 + warp;
    const float4* row4 = (const float4*)(A + (size_t)r * NN);
    int* cols = g_cols + (size_t)r * MAXDEG;
    unsigned below = (1u << lane) - 1u;
    int cnt = 0;

    #pragma unroll 4
    for (int c0 = 0; c0 < NN; c0 += 256) {
        float4 va = row4[(c0 >> 2) + lane];
        float4 vb = row4[(c0 >> 2) + 32 + lane];
        unsigned mk = 0;
        mk |= (va.x != 0.0f) ? 1u   : 0u;
        mk |= (va.y != 0.0f) ? 2u   : 0u;
        mk |= (va.z != 0.0f) ? 4u   : 0u;
        mk |= (va.w != 0.0f) ? 8u   : 0u;
        mk |= (vb.x != 0.0f) ? 16u  : 0u;
        mk |= (vb.y != 0.0f) ? 32u  : 0u;
        mk |= (vb.z != 0.0f) ? 64u  : 0u;
        mk |= (vb.w != 0.0f) ? 128u : 0u;
        int c = __popc(mk);
        int pre = 0, tot = 0;
        #pragma unroll
        for (int t = 0; t < 4; t++) {
            unsigned m = __ballot_sync(0xffffffffu, (c >> t) & 1);
            pre += __popc(m & below) << t;
            tot += __popc(m) << t;
        }
        int base = cnt + pre;
        cnt += tot;
        if (mk) {
            int cA = c0 + lane * 4, cB = c0 + 128 + lane * 4;
            if (mk & 1u)   { if (base < MAXDEG) cols[base] = cA + 0; base++; }
            if (mk & 2u)   { if (base < MAXDEG) cols[base] = cA + 1; base++; }
            if (mk & 4u)   { if (base < MAXDEG) cols[base] = cA + 2; base++; }
            if (mk & 8u)   { if (base < MAXDEG) cols[base] = cA + 3; base++; }
            if (mk & 16u)  { if (base < MAXDEG) cols[base] = cB + 0; base++; }
            if (mk & 32u)  { if (base < MAXDEG) cols[base] = cB + 1; base++; }
            if (mk & 64u)  { if (base < MAXDEG) cols[base] = cB + 2; base++; }
            if (mk & 128u) { if (base < MAXDEG) cols[base] = cB + 3; base++; }
        }
    }
    if (lane == 0) {
        int d = cnt < MAXDEG ? cnt : MAXDEG;
        float D = (float)cnt + 1.0f;    // self loop
        g_meta[r] = make_float4(1.0f / sqrtf(D), D, __int_as_float(d), 0.0f);
    }
    if (blockIdx.x == 0 && threadIdx.x == 0) {
        float g0 = expf(lg0p[0]);
        float rr = 1.0f / (1.0f + expf(-rawp[0]));
        float gk = g0;
        #pragma unroll
        for (int k = 0; k < K_STEPS; k++) { g_lam[k] = gk / SCAD_A; gk *= rr; }
    }
}

// ============================================================================
// Kernel 2: mlp_fused — 512 threads, k-split 2 groups of 256.
// Group g computes the partial sum over its tile range into registers; group 0
// deposits partials in smem; group 1 combines, applies bias+relu into Hs;
// then F0 = Hs@w2+b2. 128 blocks, 32 rows each.
// ============================================================================
__global__ __launch_bounds__(512, 2)
void mlp_fused(const float* __restrict__ X,
               const float* __restrict__ w1,
               const float* __restrict__ b1,
               const float* __restrict__ w2,
               const float* __restrict__ b2) {
    __shared__ __align__(16) ull   Xd[2][2][KT][33];    // [group][buf][k][m] dup pairs
    __shared__ __align__(16) float Wsm[2][2][KT][HID];  // [group][buf][k][n]
    __shared__ __align__(16) ull   comb[256][4];        // group0 partials
    __shared__ float Hs[32][65];
    __shared__ float F0s[32][8];
    __shared__ float w2s[HID * OUT_DIM];
    __shared__ float b2s[OUT_DIM];
    int tid = threadIdx.x;
    int g   = tid >> 8;          // 0 / 1
    int gt  = tid & 255;
    int m0 = blockIdx.x * 32;
    int tx = gt & 15;            // col group c0 = tx*4
    int ty = gt >> 4;            // rows ty*2, ty*2+1
    int barid = 1 + g;
    int t0 = g ? TSPLIT : 0;
    int t1 = g ? NTILE : TSPLIT;
    ull acc[2][2] = {{0ull, 0ull}, {0ull, 0ull}};

    for (int idx = tid; idx < HID * OUT_DIM; idx += 512) w2s[idx] = w2[idx];
    if (tid < OUT_DIM) b2s[tid] = b2[tid];

    float xr0, xr1, xr2, xr3;
    int xrow = gt >> 3;
    int xk   = (gt & 7) * 4;
    float4 wr[2];
    const float* xrow_p = X + (size_t)(m0 + xrow) * IN_DIM;
    {
        int kt = t0 * KT;       // both groups' first tile fully in range
        xr0 = xrow_p[kt + xk + 0]; xr1 = xrow_p[kt + xk + 1];
        xr2 = xrow_p[kt + xk + 2]; xr3 = xrow_p[kt + xk + 3];
        #pragma unroll
        for (int j = 0; j < 2; j++) {
            int f4 = gt + j * 256;
            int k = kt + (f4 >> 4), n4 = f4 & 15;
            wr[j] = *(const float4*)(w1 + (size_t)k * HID + n4 * 4);
        }
    }

    for (int t = t0; t < t1; t++) {
        int buf = t & 1;
        asm volatile("bar.sync %0, %1;" :: "r"(barid), "r"(256) : "memory");
        Xd[g][buf][xk + 0][xrow] = pack_dup(xr0);
        Xd[g][buf][xk + 1][xrow] = pack_dup(xr1);
        Xd[g][buf][xk + 2][xrow] = pack_dup(xr2);
        Xd[g][buf][xk + 3][xrow] = pack_dup(xr3);
        #pragma unroll
        for (int j = 0; j < 2; j++) {
            int f4 = gt + j * 256;
            int k = f4 >> 4, n4 = f4 & 15;
            *(float4*)&Wsm[g][buf][k][n4 * 4] = wr[j];
        }
        if (t + 1 < t1) {
            int kt = (t + 1) * KT;
            if (kt + KT <= IN_DIM) {
                xr0 = xrow_p[kt + xk + 0]; xr1 = xrow_p[kt + xk + 1];
                xr2 = xrow_p[kt + xk + 2]; xr3 = xrow_p[kt + xk + 3];
                #pragma unroll
                for (int j = 0; j < 2; j++) {
                    int f4 = gt + j * 256;
                    int k = kt + (f4 >> 4), n4 = f4 & 15;
                    wr[j] = *(const float4*)(w1 + (size_t)k * HID + n4 * 4);
                }
            } else {
                xr0 = (kt + xk + 0 < IN_DIM) ? xrow_p[kt + xk + 0] : 0.0f;
                xr1 = (kt + xk + 1 < IN_DIM) ? xrow_p[kt + xk + 1] : 0.0f;
                xr2 = (kt + xk + 2 < IN_DIM) ? xrow_p[kt + xk + 2] : 0.0f;
                xr3 = (kt + xk + 3 < IN_DIM) ? xrow_p[kt + xk + 3] : 0.0f;
                #pragma unroll
                for (int j = 0; j < 2; j++) {
                    int f4 = gt + j * 256;
                    int k = kt + (f4 >> 4), n4 = f4 & 15;
                    wr[j] = (k < IN_DIM)
                          ? *(const float4*)(w1 + (size_t)k * HID + n4 * 4)
                          : make_float4(0.f, 0.f, 0.f, 0.f);
                }
            }
        }
        asm volatile("bar.sync %0, %1;" :: "r"(barid), "r"(256) : "memory");
        #pragma unroll
        for (int k = 0; k < KT; k++) {
            ull ar0 = Xd[g][buf][k][ty * 2];
            ull ar1 = Xd[g][buf][k][ty * 2 + 1];
            ulonglong2 b = *(const ulonglong2*)&Wsm[g][buf][k][tx * 4];
            fma2(acc[0][0], ar0, b.x);
            fma2(acc[0][1], ar0, b.y);
            fma2(acc[1][0], ar1, b.x);
            fma2(acc[1][1], ar1, b.y);
        }
    }

    // combine the two k-partials
    __syncthreads();
    if (g == 0) {
        comb[gt][0] = acc[0][0];
        comb[gt][1] = acc[0][1];
        comb[gt][2] = acc[1][0];
        comb[gt][3] = acc[1][1];
    }
    __syncthreads();
    if (g == 1) {
        float4 bv = *(const float4*)&b1[tx * 4];
        #pragma unroll
        for (int r = 0; r < 2; r++) {
            int rl = ty * 2 + r;
            float p0, p1, p2, p3, q0, q1, q2, q3;
            unpack2(acc[r][0], p0, p1);
            unpack2(acc[r][1], p2, p3);
            unpack2(comb[gt][r * 2 + 0], q0, q1);
            unpack2(comb[gt][r * 2 + 1], q2, q3);
            Hs[rl][tx * 4 + 0] = fmaxf(p0 + q0 + bv.x, 0.0f);
            Hs[rl][tx * 4 + 1] = fmaxf(p1 + q1 + bv.y, 0.0f);
            Hs[rl][tx * 4 + 2] = fmaxf(p2 + q2 + bv.z, 0.0f);
            Hs[rl][tx * 4 + 3] = fmaxf(p3 + q3 + bv.w, 0.0f);
        }
    }
    __syncthreads();

    // mlp2: 224 threads, one (row, out) each
    if (tid < 32 * OUT_DIM) {
        int o = tid >> 5, r = tid & 31;
        float a = b2s[o];
        #pragma unroll 16
        for (int k = 0; k < HID; k++) a = fmaf(Hs[r][k], w2s[k * OUT_DIM + o], a);
        F0s[r][o] = a;
    }
    __syncthreads();

    if (tid < 32) {
        int row = m0 + tid;
        #pragma unroll
        for (int o = 0; o < 7; o++) g_F0[row * 8 + o] = F0s[tid][o];
        g_F0[row * 8 + 7] = 0.0f;
    }
}

// ============================================================================
// Kernel 3: persistent iterations — 512 blocks x 256 threads, warp per row.
// One Nd buffer per step (write-once st.cg, read-once cached next step:
// reader first-touch => no stale-L1 hazard); cols/meta/F0 L1-hot across steps.
// ============================================================================
__device__ __forceinline__ void bar_arrive_wait(unsigned target_epoch) {
    __syncthreads();
    if (threadIdx.x == 0) {
        unsigned old;
        asm volatile("atom.add.acq_rel.gpu.u32 %0, [%1], %2;"
                     : "=r"(old) : "l"(&g_bar_cnt), "r"(1u) : "memory");
        if (old == target_epoch * (unsigned)IBLK - 1u) {
            asm volatile("st.release.gpu.u32 [%0], %1;"
                         :: "l"(&g_bar_epoch), "r"(target_epoch) : "memory");
        } else {
            unsigned e;
            do {
                asm volatile("ld.acquire.gpu.u32 %0, [%1];"
                             : "=r"(e) : "l"(&g_bar_epoch) : "memory");
            } while ((int)(e - target_epoch) < 0);
        }
    }
    __syncthreads();
}

__global__ __launch_bounds__(256, 4)
void iter_persistent(float* __restrict__ out) {
    __shared__ unsigned ep0s;
    int tid = threadIdx.x;
    int lane = tid & 31;
    int g = lane & 7;
    int i = blockIdx.x * 8 + (tid >> 5);     // warp per row

    if (tid == 0) {
        unsigned e;
        asm volatile("ld.acquire.gpu.u32 %0, [%1];" : "=r"(e)
                     : "l"(&g_bar_epoch) : "memory");
        ep0s = e;
    }

    float4 meta = g_meta[i];
    float rdi = meta.x, Di = meta.y;
    int deg = __float_as_int(meta.z);
    float F0g = g_F0[(size_t)i * 8 + g];     // slot 7 = 0
    const int* cols = g_cols + (size_t)i * MAXDEG;
    __syncthreads();
    unsigned ep0 = ep0s;

    // prologue: seed buf 0 with {Fn = F0/sqrt(D), sq}
    {
        float fn = F0g * rdi;
        float c = (g < 7) ? fn * fn : 0.0f;
        c += shx(c, 1);
        c += shx(c, 2);
        c += shx(c, 4);
        if (lane < 8)
            __stcg(&g_Nd[(size_t)i * 8 + g], (g < 7) ? fn : c);
    }
    bar_arrive_wait(ep0 + 1);

    #pragma unroll 1
    for (int k = 0; k < K_STEPS; k++) {
        const float* Ndin  = g_Nd + (size_t)k * (NN * 8);
        float*       Ndout = g_Nd + (size_t)(k + 1) * (NN * 8);
        float lam = g_lam[k];
        float alam = SCAD_A * lam;

        const float4* ndi = (const float4*)(Ndin + (size_t)i * 8);
        float4 f0 = ndi[0], f1 = ndi[1];
        float fni[7] = {f0.x, f0.y, f0.z, f0.w, f1.x, f1.y, f1.z};
        float sqi = f1.w;

        float t0 = 0.f, t1 = 0.f, t2 = 0.f, t3 = 0.f,
              t4 = 0.f, t5 = 0.f, t6 = 0.f, t7 = 0.f;   // t7 = s

        for (int e = lane; e < deg; e += 32) {
            int j = cols[e];
            const float4* nj = (const float4*)(Ndin + (size_t)j * 8);
            float4 a0 = nj[0], a1 = nj[1];
            float dot = fni[0] * a0.x + fni[1] * a0.y + fni[2] * a0.z
                      + fni[3] * a0.w + fni[4] * a1.x + fni[5] * a1.y
                      + fni[6] * a1.z;
            float Z = fmaxf(sqi + a1.w - 2.0f * dot, 0.0f);
            float y = sqrtf(Z);
            float w;
            if (y <= lam)        w = 1.0f;
            else if (y <= alam)  w = __fdividef(alam - y,
                                                (SCAD_A - 1.0f) * fmaxf(y, 1e-12f));
            else                 w = 0.0f;
            t7 += w;
            t0 = fmaf(w, a0.x, t0);
            t1 = fmaf(w, a0.y, t1);
            t2 = fmaf(w, a0.z, t2);
            t3 = fmaf(w, a0.w, t3);
            t4 = fmaf(w, a1.x, t4);
            t5 = fmaf(w, a1.y, t5);
            t6 = fmaf(w, a1.z, t6);
        }

        // transposing tree reduce within each 8-lane group (7 shfls)
        bool h4 = (g & 4) != 0, h2 = (g & 2) != 0, h1 = (g & 1) != 0;
        float r0 = shx(h4 ? t0 : t4, 4);
        float r1 = shx(h4 ? t1 : t5, 4);
        float r2 = shx(h4 ? t2 : t6, 4);
        float r3 = shx(h4 ? t3 : t7, 4);
        float u0 = (h4 ? t4 : t0) + r0;
        float u1 = (h4 ? t5 : t1) + r1;
        float u2 = (h4 ? t6 : t2) + r2;
        float u3 = (h4 ? t7 : t3) + r3;
        r0 = shx(h2 ? u0 : u2, 2);
        r1 = shx(h2 ? u1 : u3, 2);
        float w0 = (h2 ? u2 : u0) + r0;
        float w1 = (h2 ? u3 : u1) + r1;
        r0 = shx(h1 ? w0 : w1, 1);
        float tot = (h1 ? w1 : w0) + r0;
        tot += shx(tot, 8);
        tot += shx(tot, 16);

        float sT = __shfl_sync(0xffffffffu, tot, 7, 8);   // comp 7 = s
        float Q = sT / Di + LAMW;
        float invQ = 1.0f / Q;
        float f = (rdi * tot + LAMW * F0g) * invQ;

        if (k == K_STEPS - 1) {
            if (lane < 7) out[(size_t)i * OUT_DIM + g] = f;
        } else {
            float fn = f * rdi;
            float c = (g < 7) ? fn * fn : 0.0f;
            c += shx(c, 1);
            c += shx(c, 2);
            c += shx(c, 4);
            if (lane < 8)
                __stcg(&Ndout[(size_t)i * 8 + g], (g < 7) ? fn : c);
            bar_arrive_wait(ep0 + 2 + (unsigned)k);
        }
    }
}

// ---------------- launch ----------------
extern "C" void kernel_launch(void* const* d_in, const int* in_sizes, int n_in,
                              void* d_out, int out_size) {
    const float *A = nullptr, *X = nullptr, *w1 = nullptr, *b1 = nullptr,
                *w2 = nullptr, *b2 = nullptr, *lg0 = nullptr, *raw = nullptr;
    for (int t = 0; t < n_in; t++) {
        int sz = in_sizes[t];
        const float* p = (const float*)d_in[t];
        if      (sz == NN * NN)        A  = p;
        else if (sz == NN * IN_DIM)    X  = p;
        else if (sz == IN_DIM * HID)   w1 = p;
        else if (sz == HID)            b1 = p;
        else if (sz == HID * OUT_DIM)  w2 = p;
        else if (sz == OUT_DIM)        b2 = p;
        else if (sz == 1) { if (!lg0) lg0 = p; else raw = p; }
    }
    float* out = (float*)d_out;

    build_adj<<<512, 256>>>(A, lg0, raw);
    mlp_fused<<<128, 512>>>(X, w1, b1, w2, b2);
    iter_persistent<<<IBLK, 256>>>(out);
}

// round 15
// speedup vs baseline: 1.3748x; 1.0876x over previous
#include <cuda_runtime.h>
#include <cuda_bf16.h>
#include <math.h>

#define NN 4096
#define IN_DIM 1433
#define HID 64
#define OUT_DIM 7
#define MAXDEG 160
#define SCAD_A 3.7f
#define LAMW ((float)(1.0/0.9 - 1.0))
#define K_STEPS 10
#define KT 32
#define NTILE 45                          // ceil(1433/32)
#define IBLK 512                          // persistent grid
#define SLOTS 16                          // barrier slot arrivals (512/32)

// mlp dynamic smem layout
#define XP_BYTES (16 * 34 * 8)            // ull[16][34] = 4352
#define WS_BYTES (32 * 68 * 4)            // float[32][68] = 8704
#define GRP_BYTES (XP_BYTES + WS_BYTES)   // 13056
#define MLP_DSM (4 * GRP_BYTES)           // 52224

// ---------------- device globals ----------------
__device__ float  g_F0[NN * 8];
__device__ float  g_Nd[(K_STEPS + 1) * NN * 8];
__device__ float4 g_meta[NN];              // {rD, D, deg(bits), 0}
__device__ float  g_lam[K_STEPS];
__device__ int    g_cols[NN * MAXDEG];
__device__ unsigned g_slot[32 * 32];       // 32 counters, 128B apart
__device__ unsigned g_root;
__device__ unsigned g_bar_epoch;

typedef unsigned long long ull;

__device__ __forceinline__ ull pack_dup(float v) {
    ull r; asm("mov.b64 %0, {%1, %1};" : "=l"(r) : "f"(v)); return r;
}
__device__ __forceinline__ ull pack2(float lo, float hi) {
    ull r; asm("mov.b64 %0, {%1, %2};" : "=l"(r) : "f"(lo), "f"(hi)); return r;
}
__device__ __forceinline__ void fma2(ull& d, ull a, ull b) {
    asm("fma.rn.f32x2 %0, %1, %2, %0;" : "+l"(d) : "l"(a), "l"(b));
}
__device__ __forceinline__ void unpack2(ull p, float& lo, float& hi) {
    asm("mov.b64 {%0, %1}, %2;" : "=f"(lo), "=f"(hi) : "l"(p));
}
__device__ __forceinline__ float shx(float v, int m) {
    return __shfl_xor_sync(0xffffffffu, v, m);
}

// ============================================================================
// Kernel 1: adjacency — one row per warp, 512 blocks x 256 threads (unchanged)
// ============================================================================
__global__ __launch_bounds__(256)
void build_adj(const float* __restrict__ A,
               const float* __restrict__ lg0p,
               const float* __restrict__ rawp) {
    int warp = threadIdx.x >> 5, lane = threadIdx.x & 31;
    int r = blockIdx.x * 8 + warp;
    const float4* row4 = (const float4*)(A + (size_t)r * NN);
    int* cols = g_cols + (size_t)r * MAXDEG;
    unsigned below = (1u << lane) - 1u;
    int cnt = 0;

    #pragma unroll 4
    for (int c0 = 0; c0 < NN; c0 += 256) {
        float4 va = row4[(c0 >> 2) + lane];
        float4 vb = row4[(c0 >> 2) + 32 + lane];
        unsigned mk = 0;
        mk |= (va.x != 0.0f) ? 1u   : 0u;
        mk |= (va.y != 0.0f) ? 2u   : 0u;
        mk |= (va.z != 0.0f) ? 4u   : 0u;
        mk |= (va.w != 0.0f) ? 8u   : 0u;
        mk |= (vb.x != 0.0f) ? 16u  : 0u;
        mk |= (vb.y != 0.0f) ? 32u  : 0u;
        mk |= (vb.z != 0.0f) ? 64u  : 0u;
        mk |= (vb.w != 0.0f) ? 128u : 0u;
        int c = __popc(mk);
        int pre = 0, tot = 0;
        #pragma unroll
        for (int t = 0; t < 4; t++) {
            unsigned m = __ballot_sync(0xffffffffu, (c >> t) & 1);
            pre += __popc(m & below) << t;
            tot += __popc(m) << t;
        }
        int base = cnt + pre;
        cnt += tot;
        if (mk) {
            int cA = c0 + lane * 4, cB = c0 + 128 + lane * 4;
            if (mk & 1u)   { if (base < MAXDEG) cols[base] = cA + 0; base++; }
            if (mk & 2u)   { if (base < MAXDEG) cols[base] = cA + 1; base++; }
            if (mk & 4u)   { if (base < MAXDEG) cols[base] = cA + 2; base++; }
            if (mk & 8u)   { if (base < MAXDEG) cols[base] = cA + 3; base++; }
            if (mk & 16u)  { if (base < MAXDEG) cols[base] = cB + 0; base++; }
            if (mk & 32u)  { if (base < MAXDEG) cols[base] = cB + 1; base++; }
            if (mk & 64u)  { if (base < MAXDEG) cols[base] = cB + 2; base++; }
            if (mk & 128u) { if (base < MAXDEG) cols[base] = cB + 3; base++; }
        }
    }
    if (lane == 0) {
        int d = cnt < MAXDEG ? cnt : MAXDEG;
        float D = (float)cnt + 1.0f;    // self loop
        g_meta[r] = make_float4(1.0f / sqrtf(D), D, __int_as_float(d), 0.0f);
    }
    if (blockIdx.x == 0 && threadIdx.x == 0) {
        float g0 = expf(lg0p[0]);
        float rr = 1.0f / (1.0f + expf(-rawp[0]));
        float gk = g0;
        #pragma unroll
        for (int k = 0; k < K_STEPS; k++) { g_lam[k] = gk / SCAD_A; gk *= rr; }
    }
}

// ============================================================================
// Kernel 2: mlp v3 — 128 blocks x 512 threads, 4 k-groups x 128.
// R4xC4 per thread, X packed as row-pairs (no dup), W dup'd in registers.
// 2 B of smem traffic per FMA (crossbar floor ~22us chip-wide).
// ============================================================================
__global__ __launch_bounds__(512)
void mlp_fused(const float* __restrict__ X,
               const float* __restrict__ w1,
               const float* __restrict__ b1,
               const float* __restrict__ w2,
               const float* __restrict__ b2) {
    extern __shared__ __align__(16) char dsm[];
    __shared__ float Hs[32][65];
    __shared__ float F0s[32][8];
    __shared__ float w2s[HID * OUT_DIM];
    __shared__ float b2s[OUT_DIM];

    int tid = threadIdx.x;
    int g   = tid >> 7;               // k-group 0..3
    int gt  = tid & 127;
    int m0  = blockIdx.x * 32;
    int tx  = gt & 15;                // cols tx*4..+3
    int ty  = gt >> 4;                // rows ty*4..+3  (ty in 0..7)
    int barid = 1 + g;
    const int TB[5] = {0, 12, 23, 34, 45};
    int t0 = TB[g], t1 = TB[g + 1];

    ull* Xp  = (ull*)(dsm + g * GRP_BYTES);              // [16][34]
    float* Ws = (float*)(dsm + g * GRP_BYTES + XP_BYTES); // [32][68]

    for (int idx = tid; idx < HID * OUT_DIM; idx += 512) w2s[idx] = w2[idx];
    if (tid < OUT_DIM) b2s[tid] = b2[tid];

    ull acc[2][4] = {{0ull,0ull,0ull,0ull},{0ull,0ull,0ull,0ull}};

    // staging map
    int rp_s = gt >> 3;               // 0..15 (row pair)
    int k4   = (gt & 7) * 4;          // 0..28
    const float* xa_p = X + (size_t)(m0 + 2 * rp_s) * IN_DIM;
    const float* xb_p = xa_p + IN_DIM;
    float xa[4], xb[4];
    float4 wr[4];

    // prefetch tile t0
    {
        int K0 = t0 * KT;
        #pragma unroll
        for (int j = 0; j < 4; j++) {
            int kk = K0 + k4 + j;
            xa[j] = (kk < IN_DIM) ? xa_p[kk] : 0.0f;
            xb[j] = (kk < IN_DIM) ? xb_p[kk] : 0.0f;
        }
        #pragma unroll
        for (int j = 0; j < 4; j++) {
            int id = gt + j * 128;
            int kk = K0 + (id >> 4), n4 = id & 15;
            wr[j] = (kk < IN_DIM) ? *(const float4*)(w1 + (size_t)kk * HID + n4 * 4)
                                  : make_float4(0.f, 0.f, 0.f, 0.f);
        }
    }

    for (int t = t0; t < t1; t++) {
        asm volatile("bar.sync %0, %1;" :: "r"(barid), "r"(128) : "memory");
        // store staged X (packed row-pairs) and W
        {
            ull e0 = pack2(xa[0], xb[0]), e1 = pack2(xa[1], xb[1]);
            ull e2 = pack2(xa[2], xb[2]), e3 = pack2(xa[3], xb[3]);
            ull* dst = &Xp[rp_s * 34 + k4];
            ((ulonglong2*)dst)[0] = make_ulonglong2(e0, e1);
            ((ulonglong2*)dst)[1] = make_ulonglong2(e2, e3);
        }
        #pragma unroll
        for (int j = 0; j < 4; j++) {
            int id = gt + j * 128;
            int kk = id >> 4, n4 = id & 15;
            *(float4*)&Ws[kk * 68 + n4 * 4] = wr[j];
        }
        asm volatile("bar.sync %0, %1;" :: "r"(barid), "r"(128) : "memory");
        // prefetch next
        if (t + 1 < t1) {
            int K0 = (t + 1) * KT;
            #pragma unroll
            for (int j = 0; j < 4; j++) {
                int kk = K0 + k4 + j;
                xa[j] = (kk < IN_DIM) ? xa_p[kk] : 0.0f;
                xb[j] = (kk < IN_DIM) ? xb_p[kk] : 0.0f;
            }
            #pragma unroll
            for (int j = 0; j < 4; j++) {
                int id = gt + j * 128;
                int kk = K0 + (id >> 4), n4 = id & 15;
                wr[j] = (kk < IN_DIM) ? *(const float4*)(w1 + (size_t)kk * HID + n4 * 4)
                                      : make_float4(0.f, 0.f, 0.f, 0.f);
            }
        }
        // compute: per k 2xLDS.64 + LDS.128 + 4 dup + 8 FFMA2 (16 FMA / 32B)
        #pragma unroll
        for (int k = 0; k < KT; k++) {
            ull x0 = Xp[(ty * 2) * 34 + k];       // rows 4ty, 4ty+1
            ull x1 = Xp[(ty * 2 + 1) * 34 + k];   // rows 4ty+2, 4ty+3
            float4 wv = *(const float4*)&Ws[k * 68 + tx * 4];
            ull w0 = pack_dup(wv.x), w1d = pack_dup(wv.y);
            ull w2d = pack_dup(wv.z), w3d = pack_dup(wv.w);
            fma2(acc[0][0], x0, w0);  fma2(acc[1][0], x1, w0);
            fma2(acc[0][1], x0, w1d); fma2(acc[1][1], x1, w1d);
            fma2(acc[0][2], x0, w2d); fma2(acc[1][2], x1, w2d);
            fma2(acc[0][3], x0, w3d); fma2(acc[1][3], x1, w3d);
        }
    }

    // combine 4 k-partials: groups 1..3 deposit into aliased tile region
    __syncthreads();
    ull* comb = (ull*)dsm;
    if (g > 0) {
        int base = ((g - 1) * 128 + gt) * 8;
        #pragma unroll
        for (int rp = 0; rp < 2; rp++)
            #pragma unroll
            for (int c = 0; c < 4; c++)
                comb[base + rp * 4 + c] = acc[rp][c];
    }
    __syncthreads();
    if (g == 0) {
        float4 bv = *(const float4*)&b1[tx * 4];
        float bias[4] = {bv.x, bv.y, bv.z, bv.w};
        #pragma unroll
        for (int rp = 0; rp < 2; rp++) {
            int row0 = ty * 4 + rp * 2;
            #pragma unroll
            for (int c = 0; c < 4; c++) {
                float lo, hi;
                unpack2(acc[rp][c], lo, hi);
                #pragma unroll
                for (int p = 0; p < 3; p++) {
                    float plo, phi;
                    unpack2(comb[(p * 128 + gt) * 8 + rp * 4 + c], plo, phi);
                    lo += plo; hi += phi;
                }
                Hs[row0][tx * 4 + c]     = fmaxf(lo + bias[c], 0.0f);
                Hs[row0 + 1][tx * 4 + c] = fmaxf(hi + bias[c], 0.0f);
            }
        }
    }
    __syncthreads();

    // mlp2: 224 threads, one (row, out) each
    if (tid < 32 * OUT_DIM) {
        int o = tid >> 5, r = tid & 31;
        float a = b2s[o];
        #pragma unroll 16
        for (int k = 0; k < HID; k++) a = fmaf(Hs[r][k], w2s[k * OUT_DIM + o], a);
        F0s[r][o] = a;
    }
    __syncthreads();

    if (tid < 32) {
        int row = m0 + tid;
        #pragma unroll
        for (int o = 0; o < 7; o++) g_F0[row * 8 + o] = F0s[tid][o];
        g_F0[row * 8 + 7] = 0.0f;
    }
}

// ============================================================================
// Kernel 3: persistent iterations — 512 blocks x 256 threads, warp per row.
// Per-step Nd buffers (write-once st.cg, read-once cached next step).
// Hierarchical epoch barrier: 32 padded slot counters -> root -> epoch.
// ============================================================================
__device__ __forceinline__ void bar_arrive_wait(unsigned target_epoch) {
    __syncthreads();
    if (threadIdx.x == 0) {
        int s = blockIdx.x & 31;
        unsigned old;
        asm volatile("atom.add.acq_rel.gpu.u32 %0, [%1], %2;"
                     : "=r"(old) : "l"(&g_slot[s * 32]), "r"(1u) : "memory");
        bool done = false;
        if (old == target_epoch * (unsigned)SLOTS - 1u) {
            unsigned rold;
            asm volatile("atom.add.acq_rel.gpu.u32 %0, [%1], %2;"
                         : "=r"(rold) : "l"(&g_root), "r"(1u) : "memory");
            if (rold == target_epoch * 32u - 1u) {
                asm volatile("st.release.gpu.u32 [%0], %1;"
                             :: "l"(&g_bar_epoch), "r"(target_epoch) : "memory");
                done = true;
            }
        }
        if (!done) {
            unsigned e;
            do {
                asm volatile("ld.acquire.gpu.u32 %0, [%1];"
                             : "=r"(e) : "l"(&g_bar_epoch) : "memory");
            } while ((int)(e - target_epoch) < 0);
        }
    }
    __syncthreads();
}

__global__ __launch_bounds__(256, 4)
void iter_persistent(float* __restrict__ out) {
    __shared__ unsigned ep0s;
    int tid = threadIdx.x;
    int lane = tid & 31;
    int g = lane & 7;
    int i = blockIdx.x * 8 + (tid >> 5);     // warp per row

    if (tid == 0) {
        unsigned e;
        asm volatile("ld.acquire.gpu.u32 %0, [%1];" : "=r"(e)
                     : "l"(&g_bar_epoch) : "memory");
        ep0s = e;
    }

    float4 meta = g_meta[i];
    float rdi = meta.x, Di = meta.y;
    int deg = __float_as_int(meta.z);
    float F0g = g_F0[(size_t)i * 8 + g];     // slot 7 = 0
    const int* cols = g_cols + (size_t)i * MAXDEG;
    __syncthreads();
    unsigned ep0 = ep0s;

    // prologue: seed buf 0 with {Fn = F0/sqrt(D), sq}
    {
        float fn = F0g * rdi;
        float c = (g < 7) ? fn * fn : 0.0f;
        c += shx(c, 1);
        c += shx(c, 2);
        c += shx(c, 4);
        if (lane < 8)
            __stcg(&g_Nd[(size_t)i * 8 + g], (g < 7) ? fn : c);
    }
    bar_arrive_wait(ep0 + 1);

    #pragma unroll 1
    for (int k = 0; k < K_STEPS; k++) {
        const float* Ndin  = g_Nd + (size_t)k * (NN * 8);
        float*       Ndout = g_Nd + (size_t)(k + 1) * (NN * 8);
        float lam = g_lam[k];
        float alam = SCAD_A * lam;

        const float4* ndi = (const float4*)(Ndin + (size_t)i * 8);
        float4 f0 = ndi[0], f1 = ndi[1];
        float fni[7] = {f0.x, f0.y, f0.z, f0.w, f1.x, f1.y, f1.z};
        float sqi = f1.w;

        float t0 = 0.f, t1 = 0.f, t2 = 0.f, t3 = 0.f,
              t4 = 0.f, t5 = 0.f, t6 = 0.f, t7 = 0.f;   // t7 = s

        for (int e = lane; e < deg; e += 32) {
            int j = cols[e];
            const float4* nj = (const float4*)(Ndin + (size_t)j * 8);
            float4 a0 = nj[0], a1 = nj[1];
            float dot = fni[0] * a0.x + fni[1] * a0.y + fni[2] * a0.z
                      + fni[3] * a0.w + fni[4] * a1.x + fni[5] * a1.y
                      + fni[6] * a1.z;
            float Z = fmaxf(sqi + a1.w - 2.0f * dot, 0.0f);
            float y = sqrtf(Z);
            float w;
            if (y <= lam)        w = 1.0f;
            else if (y <= alam)  w = __fdividef(alam - y,
                                                (SCAD_A - 1.0f) * fmaxf(y, 1e-12f));
            else                 w = 0.0f;
            t7 += w;
            t0 = fmaf(w, a0.x, t0);
            t1 = fmaf(w, a0.y, t1);
            t2 = fmaf(w, a0.z, t2);
            t3 = fmaf(w, a0.w, t3);
            t4 = fmaf(w, a1.x, t4);
            t5 = fmaf(w, a1.y, t5);
            t6 = fmaf(w, a1.z, t6);
        }

        // transposing tree reduce within each 8-lane group (7 shfls)
        bool h4 = (g & 4) != 0, h2 = (g & 2) != 0, h1 = (g & 1) != 0;
        float r0 = shx(h4 ? t0 : t4, 4);
        float r1 = shx(h4 ? t1 : t5, 4);
        float r2 = shx(h4 ? t2 : t6, 4);
        float r3 = shx(h4 ? t3 : t7, 4);
        float u0 = (h4 ? t4 : t0) + r0;
        float u1 = (h4 ? t5 : t1) + r1;
        float u2 = (h4 ? t6 : t2) + r2;
        float u3 = (h4 ? t7 : t3) + r3;
        r0 = shx(h2 ? u0 : u2, 2);
        r1 = shx(h2 ? u1 : u3, 2);
        float w0 = (h2 ? u2 : u0) + r0;
        float w1 = (h2 ? u3 : u1) + r1;
        r0 = shx(h1 ? w0 : w1, 1);
        float tot = (h1 ? w1 : w0) + r0;
        tot += shx(tot, 8);
        tot += shx(tot, 16);

        float sT = __shfl_sync(0xffffffffu, tot, 7, 8);   // comp 7 = s
        float Q = sT / Di + LAMW;
        float invQ = 1.0f / Q;
        float f = (rdi * tot + LAMW * F0g) * invQ;

        if (k == K_STEPS - 1) {
            if (lane < 7) out[(size_t)i * OUT_DIM + g] = f;
        } else {
            float fn = f * rdi;
            float c = (g < 7) ? fn * fn : 0.0f;
            c += shx(c, 1);
            c += shx(c, 2);
            c += shx(c, 4);
            if (lane < 8)
                __stcg(&Ndout[(size_t)i * 8 + g], (g < 7) ? fn : c);
            bar_arrive_wait(ep0 + 2 + (unsigned)k);
        }
    }
}

// ---------------- launch ----------------
extern "C" void kernel_launch(void* const* d_in, const int* in_sizes, int n_in,
                              void* d_out, int out_size) {
    const float *A = nullptr, *X = nullptr, *w1 = nullptr, *b1 = nullptr,
                *w2 = nullptr, *b2 = nullptr, *lg0 = nullptr, *raw = nullptr;
    for (int t = 0; t < n_in; t++) {
        int sz = in_sizes[t];
        const float* p = (const float*)d_in[t];
        if      (sz == NN * NN)        A  = p;
        else if (sz == NN * IN_DIM)    X  = p;
        else if (sz == IN_DIM * HID)   w1 = p;
        else if (sz == HID)            b1 = p;
        else if (sz == HID * OUT_DIM)  w2 = p;
        else if (sz == OUT_DIM)        b2 = p;
        else if (sz == 1) { if (!lg0) lg0 = p; else raw = p; }
    }
    float* out = (float*)d_out;

    cudaFuncSetAttribute(mlp_fused,
                         cudaFuncAttributeMaxDynamicSharedMemorySize, MLP_DSM);

    build_adj<<<512, 256>>>(A, lg0, raw);
    mlp_fused<<<128, 512, MLP_DSM>>>(X, w1, b1, w2, b2);
    iter_persistent<<<IBLK, 256>>>(out);
}

// round 17
// speedup vs baseline: 1.3944x; 1.0143x over previous
#include <cuda_runtime.h>
#include <cuda_bf16.h>
#include <math.h>

#define NN 4096
#define IN_DIM 1433
#define HID 64
#define OUT_DIM 7
#define MAXDEG 160
#define SCAD_A 3.7f
#define LAMW ((float)(1.0/0.9 - 1.0))
#define K_STEPS 10
#define KT 32
#define NTILE 45                          // ceil(1433/32)
#define IBLK 512                          // persistent grid
#define SLOTS 16                          // barrier slot arrivals (512/32)

// mlp dynamic smem layout
#define XP_BYTES (16 * 34 * 8)            // ull[16][34] = 4352
#define WS_BYTES (32 * 68 * 4)            // float[32][68] = 8704
#define GRP_BYTES (XP_BYTES + WS_BYTES)   // 13056
#define MLP_DSM (4 * GRP_BYTES)           // 52224

// ---------------- device globals ----------------
__device__ float  g_F0[NN * 8];
__device__ float  g_Nd[(K_STEPS + 1) * NN * 8];
__device__ float4 g_meta[NN];              // {rD, D, deg(bits), 0}
__device__ float  g_lam[K_STEPS];
__device__ int    g_cols[NN * MAXDEG];
__device__ unsigned g_slot[32 * 32];       // 32 counters, 128B apart
__device__ unsigned g_root;
__device__ unsigned g_bar_epoch;

typedef unsigned long long ull;

__device__ __forceinline__ ull pack_dup(float v) {
    ull r; asm("mov.b64 %0, {%1, %1};" : "=l"(r) : "f"(v)); return r;
}
__device__ __forceinline__ ull pack2(float lo, float hi) {
    ull r; asm("mov.b64 %0, {%1, %2};" : "=l"(r) : "f"(lo), "f"(hi)); return r;
}
__device__ __forceinline__ void fma2(ull& d, ull a, ull b) {
    asm("fma.rn.f32x2 %0, %1, %2, %0;" : "+l"(d) : "l"(a), "l"(b));
}
__device__ __forceinline__ void unpack2(ull p, float& lo, float& hi) {
    asm("mov.b64 {%0, %1}, %2;" : "=f"(lo), "=f"(hi) : "l"(p));
}
__device__ __forceinline__ float shx(float v, int m) {
    return __shfl_xor_sync(0xffffffffu, v, m);
}

// ============================================================================
// Kernel 1: adjacency — one row per warp, 512 blocks x 256 threads (unchanged)
// ============================================================================
__global__ __launch_bounds__(256)
void build_adj(const float* __restrict__ A,
               const float* __restrict__ lg0p,
               const float* __restrict__ rawp) {
    int warp = threadIdx.x >> 5, lane = threadIdx.x & 31;
    int r = blockIdx.x * 8 + warp;
    const float4* row4 = (const float4*)(A + (size_t)r * NN);
    int* cols = g_cols + (size_t)r * MAXDEG;
    unsigned below = (1u << lane) - 1u;
    int cnt = 0;

    #pragma unroll 4
    for (int c0 = 0; c0 < NN; c0 += 256) {
        float4 va = row4[(c0 >> 2) + lane];
        float4 vb = row4[(c0 >> 2) + 32 + lane];
        unsigned mk = 0;
        mk |= (va.x != 0.0f) ? 1u   : 0u;
        mk |= (va.y != 0.0f) ? 2u   : 0u;
        mk |= (va.z != 0.0f) ? 4u   : 0u;
        mk |= (va.w != 0.0f) ? 8u   : 0u;
        mk |= (vb.x != 0.0f) ? 16u  : 0u;
        mk |= (vb.y != 0.0f) ? 32u  : 0u;
        mk |= (vb.z != 0.0f) ? 64u  : 0u;
        mk |= (vb.w != 0.0f) ? 128u : 0u;
        int c = __popc(mk);
        int pre = 0, tot = 0;
        #pragma unroll
        for (int t = 0; t < 4; t++) {
            unsigned m = __ballot_sync(0xffffffffu, (c >> t) & 1);
            pre += __popc(m & below) << t;
            tot += __popc(m) << t;
        }
        int base = cnt + pre;
        cnt += tot;
        if (mk) {
            int cA = c0 + lane * 4, cB = c0 + 128 + lane * 4;
            if (mk & 1u)   { if (base < MAXDEG) cols[base] = cA + 0; base++; }
            if (mk & 2u)   { if (base < MAXDEG) cols[base] = cA + 1; base++; }
            if (mk & 4u)   { if (base < MAXDEG) cols[base] = cA + 2; base++; }
            if (mk & 8u)   { if (base < MAXDEG) cols[base] = cA + 3; base++; }
            if (mk & 16u)  { if (base < MAXDEG) cols[base] = cB + 0; base++; }
            if (mk & 32u)  { if (base < MAXDEG) cols[base] = cB + 1; base++; }
            if (mk & 64u)  { if (base < MAXDEG) cols[base] = cB + 2; base++; }
            if (mk & 128u) { if (base < MAXDEG) cols[base] = cB + 3; base++; }
        }
    }
    if (lane == 0) {
        int d = cnt < MAXDEG ? cnt : MAXDEG;
        float D = (float)cnt + 1.0f;    // self loop
        g_meta[r] = make_float4(1.0f / sqrtf(D), D, __int_as_float(d), 0.0f);
    }
    if (blockIdx.x == 0 && threadIdx.x == 0) {
        float g0 = expf(lg0p[0]);
        float rr = 1.0f / (1.0f + expf(-rawp[0]));
        float gk = g0;
        #pragma unroll
        for (int k = 0; k < K_STEPS; k++) { g_lam[k] = gk / SCAD_A; gk *= rr; }
    }
}

// ============================================================================
// Kernel 2: mlp v3 — 128 blocks x 512 threads, 4 k-groups x 128 (unchanged)
// ============================================================================
__global__ __launch_bounds__(512)
void mlp_fused(const float* __restrict__ X,
               const float* __restrict__ w1,
               const float* __restrict__ b1,
               const float* __restrict__ w2,
               const float* __restrict__ b2) {
    extern __shared__ __align__(16) char dsm[];
    __shared__ float Hs[32][65];
    __shared__ float F0s[32][8];
    __shared__ float w2s[HID * OUT_DIM];
    __shared__ float b2s[OUT_DIM];

    int tid = threadIdx.x;
    int g   = tid >> 7;               // k-group 0..3
    int gt  = tid & 127;
    int m0  = blockIdx.x * 32;
    int tx  = gt & 15;                // cols tx*4..+3
    int ty  = gt >> 4;                // rows ty*4..+3
    int barid = 1 + g;
    const int TB[5] = {0, 12, 23, 34, 45};
    int t0 = TB[g], t1 = TB[g + 1];

    ull* Xp  = (ull*)(dsm + g * GRP_BYTES);               // [16][34]
    float* Ws = (float*)(dsm + g * GRP_BYTES + XP_BYTES); // [32][68]

    for (int idx = tid; idx < HID * OUT_DIM; idx += 512) w2s[idx] = w2[idx];
    if (tid < OUT_DIM) b2s[tid] = b2[tid];

    ull acc[2][4] = {{0ull,0ull,0ull,0ull},{0ull,0ull,0ull,0ull}};

    int rp_s = gt >> 3;               // 0..15 (row pair)
    int k4   = (gt & 7) * 4;          // 0..28
    const float* xa_p = X + (size_t)(m0 + 2 * rp_s) * IN_DIM;
    const float* xb_p = xa_p + IN_DIM;
    float xa[4], xb[4];
    float4 wr[4];

    {
        int K0 = t0 * KT;
        #pragma unroll
        for (int j = 0; j < 4; j++) {
            int kk = K0 + k4 + j;
            xa[j] = (kk < IN_DIM) ? xa_p[kk] : 0.0f;
            xb[j] = (kk < IN_DIM) ? xb_p[kk] : 0.0f;
        }
        #pragma unroll
        for (int j = 0; j < 4; j++) {
            int id = gt + j * 128;
            int kk = K0 + (id >> 4), n4 = id & 15;
            wr[j] = (kk < IN_DIM) ? *(const float4*)(w1 + (size_t)kk * HID + n4 * 4)
                                  : make_float4(0.f, 0.f, 0.f, 0.f);
        }
    }

    for (int t = t0; t < t1; t++) {
        asm volatile("bar.sync %0, %1;" :: "r"(barid), "r"(128) : "memory");
        {
            ull e0 = pack2(xa[0], xb[0]), e1 = pack2(xa[1], xb[1]);
            ull e2 = pack2(xa[2], xb[2]), e3 = pack2(xa[3], xb[3]);
            ull* dst = &Xp[rp_s * 34 + k4];
            ((ulonglong2*)dst)[0] = make_ulonglong2(e0, e1);
            ((ulonglong2*)dst)[1] = make_ulonglong2(e2, e3);
        }
        #pragma unroll
        for (int j = 0; j < 4; j++) {
            int id = gt + j * 128;
            int kk = id >> 4, n4 = id & 15;
            *(float4*)&Ws[kk * 68 + n4 * 4] = wr[j];
        }
        asm volatile("bar.sync %0, %1;" :: "r"(barid), "r"(128) : "memory");
        if (t + 1 < t1) {
            int K0 = (t + 1) * KT;
            #pragma unroll
            for (int j = 0; j < 4; j++) {
                int kk = K0 + k4 + j;
                xa[j] = (kk < IN_DIM) ? xa_p[kk] : 0.0f;
                xb[j] = (kk < IN_DIM) ? xb_p[kk] : 0.0f;
            }
            #pragma unroll
            for (int j = 0; j < 4; j++) {
                int id = gt + j * 128;
                int kk = K0 + (id >> 4), n4 = id & 15;
                wr[j] = (kk < IN_DIM) ? *(const float4*)(w1 + (size_t)kk * HID + n4 * 4)
                                      : make_float4(0.f, 0.f, 0.f, 0.f);
            }
        }
        #pragma unroll
        for (int k = 0; k < KT; k++) {
            ull x0 = Xp[(ty * 2) * 34 + k];
            ull x1 = Xp[(ty * 2 + 1) * 34 + k];
            float4 wv = *(const float4*)&Ws[k * 68 + tx * 4];
            ull w0 = pack_dup(wv.x), w1d = pack_dup(wv.y);
            ull w2d = pack_dup(wv.z), w3d = pack_dup(wv.w);
            fma2(acc[0][0], x0, w0);  fma2(acc[1][0], x1, w0);
            fma2(acc[0][1], x0, w1d); fma2(acc[1][1], x1, w1d);
            fma2(acc[0][2], x0, w2d); fma2(acc[1][2], x1, w2d);
            fma2(acc[0][3], x0, w3d); fma2(acc[1][3], x1, w3d);
        }
    }

    __syncthreads();
    ull* comb = (ull*)dsm;
    if (g > 0) {
        int base = ((g - 1) * 128 + gt) * 8;
        #pragma unroll
        for (int rp = 0; rp < 2; rp++)
            #pragma unroll
            for (int c = 0; c < 4; c++)
                comb[base + rp * 4 + c] = acc[rp][c];
    }
    __syncthreads();
    if (g == 0) {
        float4 bv = *(const float4*)&b1[tx * 4];
        float bias[4] = {bv.x, bv.y, bv.z, bv.w};
        #pragma unroll
        for (int rp = 0; rp < 2; rp++) {
            int row0 = ty * 4 + rp * 2;
            #pragma unroll
            for (int c = 0; c < 4; c++) {
                float lo, hi;
                unpack2(acc[rp][c], lo, hi);
                #pragma unroll
                for (int p = 0; p < 3; p++) {
                    float plo, phi;
                    unpack2(comb[(p * 128 + gt) * 8 + rp * 4 + c], plo, phi);
                    lo += plo; hi += phi;
                }
                Hs[row0][tx * 4 + c]     = fmaxf(lo + bias[c], 0.0f);
                Hs[row0 + 1][tx * 4 + c] = fmaxf(hi + bias[c], 0.0f);
            }
        }
    }
    __syncthreads();

    if (tid < 32 * OUT_DIM) {
        int o = tid >> 5, r = tid & 31;
        float a = b2s[o];
        #pragma unroll 16
        for (int k = 0; k < HID; k++) a = fmaf(Hs[r][k], w2s[k * OUT_DIM + o], a);
        F0s[r][o] = a;
    }
    __syncthreads();

    if (tid < 32) {
        int row = m0 + tid;
        #pragma unroll
        for (int o = 0; o < 7; o++) g_F0[row * 8 + o] = F0s[tid][o];
        g_F0[row * 8 + 7] = 0.0f;
    }
}

// ============================================================================
// Kernel 3: persistent iterations (unchanged from R15)
// ============================================================================
__device__ __forceinline__ void bar_arrive_wait(unsigned target_epoch) {
    __syncthreads();
    if (threadIdx.x == 0) {
        int s = blockIdx.x & 31;
        unsigned old;
        asm volatile("atom.add.acq_rel.gpu.u32 %0, [%1], %2;"
                     : "=r"(old) : "l"(&g_slot[s * 32]), "r"(1u) : "memory");
        bool done = false;
        if (old == target_epoch * (unsigned)SLOTS - 1u) {
            unsigned rold;
            asm volatile("atom.add.acq_rel.gpu.u32 %0, [%1], %2;"
                         : "=r"(rold) : "l"(&g_root), "r"(1u) : "memory");
            if (rold == target_epoch * 32u - 1u) {
                asm volatile("st.release.gpu.u32 [%0], %1;"
                             :: "l"(&g_bar_epoch), "r"(target_epoch) : "memory");
                done = true;
            }
        }
        if (!done) {
            unsigned e;
            do {
                asm volatile("ld.acquire.gpu.u32 %0, [%1];"
                             : "=r"(e) : "l"(&g_bar_epoch) : "memory");
            } while ((int)(e - target_epoch) < 0);
        }
    }
    __syncthreads();
}

__global__ __launch_bounds__(256, 4)
void iter_persistent(float* __restrict__ out) {
    __shared__ unsigned ep0s;
    int tid = threadIdx.x;
    int lane = tid & 31;
    int g = lane & 7;
    int i = blockIdx.x * 8 + (tid >> 5);     // warp per row

    if (tid == 0) {
        unsigned e;
        asm volatile("ld.acquire.gpu.u32 %0, [%1];" : "=r"(e)
                     : "l"(&g_bar_epoch) : "memory");
        ep0s = e;
    }

    float4 meta = g_meta[i];
    float rdi = meta.x, Di = meta.y;
    int deg = __float_as_int(meta.z);
    float F0g = g_F0[(size_t)i * 8 + g];     // slot 7 = 0
    const int* cols = g_cols + (size_t)i * MAXDEG;
    __syncthreads();
    unsigned ep0 = ep0s;

    // prologue: seed buf 0 with {Fn = F0/sqrt(D), sq}
    {
        float fn = F0g * rdi;
        float c = (g < 7) ? fn * fn : 0.0f;
        c += shx(c, 1);
        c += shx(c, 2);
        c += shx(c, 4);
        if (lane < 8)
            __stcg(&g_Nd[(size_t)i * 8 + g], (g < 7) ? fn : c);
    }
    bar_arrive_wait(ep0 + 1);

    #pragma unroll 1
    for (int k = 0; k < K_STEPS; k++) {
        const float* Ndin  = g_Nd + (size_t)k * (NN * 8);
        float*       Ndout = g_Nd + (size_t)(k + 1) * (NN * 8);
        float lam = g_lam[k];
        float alam = SCAD_A * lam;

        const float4* ndi = (const float4*)(Ndin + (size_t)i * 8);
        float4 f0 = ndi[0], f1 = ndi[1];
        float fni[7] = {f0.x, f0.y, f0.z, f0.w, f1.x, f1.y, f1.z};
        float sqi = f1.w;

        float t0 = 0.f, t1 = 0.f, t2 = 0.f, t3 = 0.f,
              t4 = 0.f, t5 = 0.f, t6 = 0.f, t7 = 0.f;   // t7 = s

        for (int e = lane; e < deg; e += 32) {
            int j = cols[e];
            const float4* nj = (const float4*)(Ndin + (size_t)j * 8);
            float4 a0 = nj[0], a1 = nj[1];
            float dot = fni[0] * a0.x + fni[1] * a0.y + fni[2] * a0.z
                      + fni[3] * a0.w + fni[4] * a1.x + fni[5] * a1.y
                      + fni[6] * a1.z;
            float Z = fmaxf(sqi + a1.w - 2.0f * dot, 0.0f);
            float y = sqrtf(Z);
            float w;
            if (y <= lam)        w = 1.0f;
            else if (y <= alam)  w = __fdividef(alam - y,
                                                (SCAD_A - 1.0f) * fmaxf(y, 1e-12f));
            else                 w = 0.0f;
            t7 += w;
            t0 = fmaf(w, a0.x, t0);
            t1 = fmaf(w, a0.y, t1);
            t2 = fmaf(w, a0.z, t2);
            t3 = fmaf(w, a0.w, t3);
            t4 = fmaf(w, a1.x, t4);
            t5 = fmaf(w, a1.y, t5);
            t6 = fmaf(w, a1.z, t6);
        }

        bool h4 = (g & 4) != 0, h2 = (g & 2) != 0, h1 = (g & 1) != 0;
        float r0 = shx(h4 ? t0 : t4, 4);
        float r1 = shx(h4 ? t1 : t5, 4);
        float r2 = shx(h4 ? t2 : t6, 4);
        float r3 = shx(h4 ? t3 : t7, 4);
        float u0 = (h4 ? t4 : t0) + r0;
        float u1 = (h4 ? t5 : t1) + r1;
        float u2 = (h4 ? t6 : t2) + r2;
        float u3 = (h4 ? t7 : t3) + r3;
        r0 = shx(h2 ? u0 : u2, 2);
        r1 = shx(h2 ? u1 : u3, 2);
        float w0 = (h2 ? u2 : u0) + r0;
        float w1 = (h2 ? u3 : u1) + r1;
        r0 = shx(h1 ? w0 : w1, 1);
        float tot = (h1 ? w1 : w0) + r0;
        tot += shx(tot, 8);
        tot += shx(tot, 16);

        float sT = __shfl_sync(0xffffffffu, tot, 7, 8);   // comp 7 = s
        float Q = sT / Di + LAMW;
        float invQ = 1.0f / Q;
        float f = (rdi * tot + LAMW * F0g) * invQ;

        if (k == K_STEPS - 1) {
            if (lane < 7) out[(size_t)i * OUT_DIM + g] = f;
        } else {
            float fn = f * rdi;
            float c = (g < 7) ? fn * fn : 0.0f;
            c += shx(c, 1);
            c += shx(c, 2);
            c += shx(c, 4);
            if (lane < 8)
                __stcg(&Ndout[(size_t)i * 8 + g], (g < 7) ? fn : c);
            bar_arrive_wait(ep0 + 2 + (unsigned)k);
        }
    }
}

// ---------------- launch: adj || mlp via forked capture branch ----------------
extern "C" void kernel_launch(void* const* d_in, const int* in_sizes, int n_in,
                              void* d_out, int out_size) {
    const float *A = nullptr, *X = nullptr, *w1 = nullptr, *b1 = nullptr,
                *w2 = nullptr, *b2 = nullptr, *lg0 = nullptr, *raw = nullptr;
    for (int t = 0; t < n_in; t++) {
        int sz = in_sizes[t];
        const float* p = (const float*)d_in[t];
        if      (sz == NN * NN)        A  = p;
        else if (sz == NN * IN_DIM)    X  = p;
        else if (sz == IN_DIM * HID)   w1 = p;
        else if (sz == HID)            b1 = p;
        else if (sz == HID * OUT_DIM)  w2 = p;
        else if (sz == OUT_DIM)        b2 = p;
        else if (sz == 1) { if (!lg0) lg0 = p; else raw = p; }
    }
    float* out = (float*)d_out;

    static bool init_done = false;
    static cudaStream_t s2;
    static cudaEvent_t ev_fork, ev_join;
    if (!init_done) {
        cudaFuncSetAttribute(mlp_fused,
                             cudaFuncAttributeMaxDynamicSharedMemorySize, MLP_DSM);
        cudaStreamCreateWithFlags(&s2, cudaStreamNonBlocking);
        cudaEventCreateWithFlags(&ev_fork, cudaEventDisableTiming);
        cudaEventCreateWithFlags(&ev_join, cudaEventDisableTiming);
        init_done = true;
    }

    // find the stream this call's default launches target (= capture stream
    // during graph capture; legacy stream otherwise)
    cudaStream_t ms = (cudaStream_t)0;
    {
        cudaStreamCaptureStatus st = cudaStreamCaptureStatusNone;
        if (cudaStreamIsCapturing(cudaStreamLegacy, &st) == cudaSuccess &&
            st == cudaStreamCaptureStatusActive) {
            ms = cudaStreamLegacy;
        } else {
            st = cudaStreamCaptureStatusNone;
            if (cudaStreamIsCapturing(cudaStreamPerThread, &st) == cudaSuccess &&
                st == cudaStreamCaptureStatusActive) {
                ms = cudaStreamPerThread;
            }
        }
    }

    // fork: adj on ms, mlp on s2 (parallel graph branches), join before iter
    cudaEventRecord(ev_fork, ms);
    cudaStreamWaitEvent(s2, ev_fork, 0);
    build_adj<<<512, 256, 0, ms>>>(A, lg0, raw);
    mlp_fused<<<128, 512, MLP_DSM, s2>>>(X, w1, b1, w2, b2);
    cudaEventRecord(ev_join, s2);
    cudaStreamWaitEvent(ms, ev_join, 0);
    iter_persistent<<<IBLK, 256, 0, ms>>>(out);
}